// round 4
// baseline (speedup 1.0000x reference)
#include <cuda_runtime.h>
#include <math.h>

#define T_ 256
#define N_ 64
#define C_ 4096
#define L_ 32
#define S_ 65           // 2*L+1
#define BLANK_ 0
#define NEGV -1e30f
#define LOG2E 1.4426950408889634f
#define LN2   0.6931471805599453f

#define TP_ (T_ + 8)    // padded T so the depth-4 pipeline never loads OOB

// Scratch, layout [n][t][s]; zero-initialized at module load.
__device__ float g_lp_ext[N_ * TP_ * S_ + 128];
__device__ float g_per_n[N_];
__device__ int   g_cnt[T_];    // rows completed per timestep (0..64)

__device__ __forceinline__ float ex2(float x) {
    float y; asm("ex2.approx.ftz.f32 %0, %1;" : "=f"(y) : "f"(x)); return y;
}
__device__ __forceinline__ float lg2(float x) {
    float y; asm("lg2.approx.ftz.f32 %0, %1;" : "=f"(y) : "f"(x)); return y;
}

__device__ __forceinline__ float ldcg(const float* p) {
    float v; asm volatile("ld.global.cg.f32 %0, [%1];" : "=f"(v) : "l"(p)); return v;
}

// 3-way / 2-way logaddexp in log2 domain. NEG sentinels: ex2(NEG-m)=0.
__device__ __forceinline__ float lae3_2(float a, float b, float c) {
    float m = fmaxf(fmaxf(a, b), c);
    float e = ex2(a - m) + ex2(b - m) + ex2(c - m);
    return m + lg2(e);
}
__device__ __forceinline__ float lae2_2(float a, float b) {
    float m = fmaxf(a, b);
    return m + lg2(ex2(a - m) + ex2(b - m));
}

// Advance the ready-watermark: counters [0, wm) are confirmed == N_.
// 32 lanes poll 32 consecutive counters at once; contiguous-prefix advance.
__device__ __forceinline__ void ensure_wm(int& wm, int target, int lane) {
    if (wm > target) return;
    const unsigned FULL = 0xffffffffu;
    while (wm <= target) {
        int idx = wm + lane;
        int c = N_;
        if (idx < T_) {
            asm volatile("ld.global.cg.s32 %0, [%1];" : "=r"(c) : "l"(g_cnt + idx));
        }
        unsigned mask = __ballot_sync(FULL, c >= N_);
        unsigned inv = ~mask;
        wm += inv ? (__ffs(inv) - 1) : 32;
    }
    __threadfence();   // acquire: order subsequent lp reads after counter observation
}

// Fused kernel. Blocks 0,1: consumers (32 warps each, 1 warp per batch n).
// Blocks 2..4097: producers, 4 (t,n) rows each (256 threads per row).
__global__ void __launch_bounds__(1024, 1) ctc_fused_kernel(
    const float* __restrict__ preds,
    const int*   __restrict__ targets,
    const int*   __restrict__ pred_lengths,
    const int*   __restrict__ target_lengths)
{
    const unsigned FULL = 0xffffffffu;
    const int tid = threadIdx.x;

    if (blockIdx.x >= 2) {
        // ───────────────────────── producer ─────────────────────────
        const int sub  = tid >> 8;          // row group 0..3
        const int gtid = tid & 255;
        const int row  = (blockIdx.x - 2) * 4 + sub;   // row = t*N + n
        const int t    = row / N_;
        const int n    = row % N_;
        const float* __restrict__ p = preds + (size_t)row * C_;

        float v[16];
        const float4* __restrict__ p4 = (const float4*)p;
        #pragma unroll
        for (int k = 0; k < 4; k++) {
            float4 f = p4[gtid + k * 256];
            v[k*4+0] = f.x; v[k*4+1] = f.y; v[k*4+2] = f.z; v[k*4+3] = f.w;
        }

        // group max
        float m = v[0];
        #pragma unroll
        for (int i = 1; i < 16; i++) m = fmaxf(m, v[i]);
        #pragma unroll
        for (int o = 16; o > 0; o >>= 1) m = fmaxf(m, __shfl_xor_sync(FULL, m, o));
        __shared__ float sm[4][8];
        if ((gtid & 31) == 0) sm[sub][gtid >> 5] = m;
        __syncthreads();
        float bm = sm[sub][0];
        #pragma unroll
        for (int i = 1; i < 8; i++) bm = fmaxf(bm, sm[sub][i]);
        __syncthreads();   // sm reused

        // group sum of exp via EX2
        const float bmL = bm * LOG2E;
        float s = 0.0f;
        #pragma unroll
        for (int i = 0; i < 16; i++) s += ex2(fmaf(v[i], LOG2E, -bmL));
        #pragma unroll
        for (int o = 16; o > 0; o >>= 1) s += __shfl_xor_sync(FULL, s, o);
        if ((gtid & 31) == 0) sm[sub][gtid >> 5] = s;
        __syncthreads();
        float bs = sm[sub][0];
        #pragma unroll
        for (int i = 1; i < 8; i++) bs += sm[sub][i];

        const float lse = bm + lg2(bs) * LN2;

        // gather 65 extended-label log2-probs into [n][t][s]
        if (gtid < S_) {
            int label = (gtid & 1) ? targets[n * L_ + (gtid >> 1)] : BLANK_;
            g_lp_ext[(n * TP_ + t) * S_ + gtid] = (p[label] - lse) * LOG2E;
        }
        __syncthreads();
        if (gtid == 0) {
            __threadfence();                 // publish row before signaling
            atomicAdd(&g_cnt[t], 1);
        }
        return;
    }

    // ───────────────────────── consumer ─────────────────────────
    const int warp = tid >> 5;
    const int lane = tid & 31;
    const int n    = blockIdx.x * 32 + warp;

    const int tl = target_lengths[n];
    const int pl = pred_lengths[n];
    const int Sv = 2 * tl + 1;
    const int s0 = 3 * lane;

    bool valid[3], skip[3];
    #pragma unroll
    for (int j = 0; j < 3; j++) {
        int s = s0 + j;
        valid[j] = (s < S_) && (s < Sv);
        bool sk = false;
        if (s < S_ && (s & 1) && s >= 2) {
            int lab  = targets[n * L_ + (s >> 1)];
            int lab2 = targets[n * L_ + (s >> 1) - 1];
            sk = (lab != BLANK_) && (lab != lab2);
        }
        skip[j] = sk;
    }

    const float* __restrict__ lp_n = g_lp_ext + n * (TP_ * S_);

    int wm = 0;
    ensure_wm(wm, 4, lane);    // rows 0..4 ready

    // alpha0 (log2 domain)
    float alpha[3];
    {
        float l0 = ldcg(lp_n + 0);
        float l1 = ldcg(lp_n + 1);
        #pragma unroll
        for (int j = 0; j < 3; j++) {
            int s = s0 + j;
            float a0 = NEGV;
            if (s == 0) a0 = l0;
            if (s == 1 && tl > 0) a0 = l1;
            alpha[j] = valid[j] ? a0 : NEGV;
        }
    }

    // preload pipeline: rows t = 1..4
    float lp[4][3];
    #pragma unroll
    for (int j = 0; j < 4; j++) {
        const float* r = lp_n + (1 + j) * S_ + s0;
        lp[j][0] = ldcg(r); lp[j][1] = ldcg(r + 1); lp[j][2] = ldcg(r + 2);
    }

    #pragma unroll 4
    for (int t = 1; t <= 256; t++) {
        const int u = (t - 1) & 3;
        float l0 = lp[u][0], l1 = lp[u][1], l2 = lp[u][2];

        // refill slot with row t+4 (ensure handles idx >= T_ as ready;
        // padded scratch keeps addresses in bounds)
        ensure_wm(wm, t + 4, lane);
        {
            const float* r = lp_n + (t + 4) * S_ + s0;
            lp[u][0] = ldcg(r); lp[u][1] = ldcg(r + 1); lp[u][2] = ldcg(r + 2);
        }

        float nb1 = __shfl_up_sync(FULL, alpha[1], 1);  // state s0-2
        float nb2 = __shfl_up_sync(FULL, alpha[2], 1);  // state s0-1
        if (lane == 0) { nb1 = NEGV; nb2 = NEGV; }

        float c0 = lae3_2(alpha[0], nb2,      skip[0] ? nb1      : NEGV);
        float c1 = lae3_2(alpha[1], alpha[0], skip[1] ? nb2      : NEGV);
        float c2 = lae3_2(alpha[2], alpha[1], skip[2] ? alpha[0] : NEGV);

        if (t < pl && t < T_) {
            alpha[0] = valid[0] ? (c0 + l0) : NEGV;
            alpha[1] = valid[1] ? (c1 + l1) : NEGV;
            alpha[2] = valid[2] ? (c2 + l2) : NEGV;
        }
    }

    // extract alpha[end], alpha[end-1] (end = 2*tl, uniform within warp)
    const int end = 2 * tl;
    const int le = end / 3, je = end % 3;
    float v0 = __shfl_sync(FULL, alpha[0], le);
    float v1 = __shfl_sync(FULL, alpha[1], le);
    float v2 = __shfl_sync(FULL, alpha[2], le);
    float a_last = (je == 0) ? v0 : (je == 1) ? v1 : v2;

    const int ep = (end > 0) ? end - 1 : 0;
    const int lpl = ep / 3, jp = ep % 3;
    float w0 = __shfl_sync(FULL, alpha[0], lpl);
    float w1 = __shfl_sync(FULL, alpha[1], lpl);
    float w2 = __shfl_sync(FULL, alpha[2], lpl);
    float a_prev = (jp == 0) ? w0 : (jp == 1) ? w1 : w2;
    if (tl <= 0) a_prev = NEGV;

    if (lane == 0) {
        float nll = -(lae2_2(a_last, a_prev) * LN2);   // back to natural log
        if (!isfinite(nll) || nll >= 1e29f) nll = 0.0f;
        int denom = tl > 0 ? tl : 1;
        g_per_n[n] = nll / (float)denom;
    }
}

// Finalize: mean over N, and reset counters for the next (deterministic) replay.
__global__ void __launch_bounds__(64) finalize_kernel(float* __restrict__ out)
{
    const int tid = threadIdx.x;

    #pragma unroll
    for (int i = tid; i < T_; i += 64) g_cnt[i] = 0;

    float v = g_per_n[tid];
    #pragma unroll
    for (int o = 16; o > 0; o >>= 1) v += __shfl_xor_sync(0xffffffffu, v, o);
    __shared__ float sw[2];
    if ((tid & 31) == 0) sw[tid >> 5] = v;
    __syncthreads();
    if (tid == 0) out[0] = (sw[0] + sw[1]) / (float)N_;
}

extern "C" void kernel_launch(void* const* d_in, const int* in_sizes, int n_in,
                              void* d_out, int out_size)
{
    const float* preds          = (const float*)d_in[0];
    const int*   targets        = (const int*)d_in[1];
    const int*   pred_lengths   = (const int*)d_in[2];
    const int*   target_lengths = (const int*)d_in[3];
    float* out = (float*)d_out;

    const int n_producer_blocks = (T_ * N_) / 4;   // 4096
    ctc_fused_kernel<<<2 + n_producer_blocks, 1024>>>(preds, targets,
                                                      pred_lengths, target_lengths);
    finalize_kernel<<<1, 64>>>(out);
}

// round 6
// speedup vs baseline: 1.4900x; 1.4900x over previous
#include <cuda_runtime.h>
#include <math.h>

#define T_ 256
#define N_ 64
#define C_ 4096
#define L_ 32
#define S_ 65           // 2*L+1
#define BLANK_ 0
#define LOG2E 1.4426950408889634f
#define LN2   0.6931471805599453f

#define TP_ (T_ + 16)   // padded T so the depth-8 pipeline never loads OOB

// Scratch, layout [n][t][s]: LINEAR probabilities of the 65 extended labels.
__device__ float g_p_ext[N_ * TP_ * S_ + 128];
__device__ float g_per_n[N_];
__device__ unsigned g_blkdone;   // zero-init; reset by last block each run

__device__ __forceinline__ float ex2(float x) {
    float y; asm("ex2.approx.ftz.f32 %0, %1;" : "=f"(y) : "f"(x)); return y;
}
__device__ __forceinline__ float lg2(float x) {
    float y; asm("lg2.approx.ftz.f32 %0, %1;" : "=f"(y) : "f"(x)); return y;
}
__device__ __forceinline__ float ldcg_f(const float* p) {
    float v; asm volatile("ld.global.cg.f32 %0, [%1];" : "=f"(v) : "l"(p)); return v;
}
__device__ __forceinline__ unsigned redux_max_u32(unsigned v) {
    unsigned r;
    asm volatile("redux.sync.max.u32 %0, %1, 0xffffffff;" : "=r"(r) : "r"(v));
    return r;
}

// Kernel 1: per (t,n) row of 4096 -> logsumexp, then gather the 65 extended-label
// probabilities (linear domain) into g_p_ext[n][t][s]. Proven at HBM roofline.
__global__ void __launch_bounds__(256) lse_gather_kernel(
    const float* __restrict__ preds, const int* __restrict__ targets)
{
    const unsigned FULL = 0xffffffffu;
    const int row = blockIdx.x;        // row = t*N + n  (preds is (T,N,C))
    const int t   = row / N_;
    const int n   = row % N_;
    const float* __restrict__ p = preds + (size_t)row * C_;
    const int tid = threadIdx.x;

    float v[16];
    const float4* __restrict__ p4 = (const float4*)p;
    #pragma unroll
    for (int k = 0; k < 4; k++) {
        float4 f = p4[tid + k * 256];
        v[k*4+0] = f.x; v[k*4+1] = f.y; v[k*4+2] = f.z; v[k*4+3] = f.w;
    }

    // block max
    float m = v[0];
    #pragma unroll
    for (int i = 1; i < 16; i++) m = fmaxf(m, v[i]);
    #pragma unroll
    for (int o = 16; o > 0; o >>= 1) m = fmaxf(m, __shfl_xor_sync(FULL, m, o));
    __shared__ float sm[8];
    if ((tid & 31) == 0) sm[tid >> 5] = m;
    __syncthreads();
    float bm = sm[0];
    #pragma unroll
    for (int i = 1; i < 8; i++) bm = fmaxf(bm, sm[i]);
    __syncthreads();   // sm reused

    // block sum of exp via EX2
    const float bmL = bm * LOG2E;
    float s = 0.0f;
    #pragma unroll
    for (int i = 0; i < 16; i++) s += ex2(fmaf(v[i], LOG2E, -bmL));
    #pragma unroll
    for (int o = 16; o > 0; o >>= 1) s += __shfl_xor_sync(FULL, s, o);
    if ((tid & 31) == 0) sm[tid >> 5] = s;
    __syncthreads();
    float bs = sm[0];
    #pragma unroll
    for (int i = 1; i < 8; i++) bs += sm[i];

    const float lse = bm + lg2(bs) * LN2;

    // gather: store LINEAR prob exp(logit - lse) in [0,1]
    if (tid < S_) {
        int label = (tid & 1) ? targets[n * L_ + (tid >> 1)] : BLANK_;
        g_p_ext[(n * TP_ + t) * S_ + tid] = ex2((p[label] - lse) * LOG2E);
    }
}

// Kernel 2: CTC forward recursion in LINEAR domain with exponent tracking.
// One warp per batch n; lane l owns states {3l,3l+1,3l+2}. Per step:
// alpha(s) = (a(s)+a(s-1)+skip*a(s-2)) * p. Rescale every 4 steps via redux-max.
// Last-finished block computes the mean (threadfence reduction, no waiting).
__global__ void __launch_bounds__(128) ctc_forward_kernel(
    const int* __restrict__ targets,
    const int* __restrict__ pred_lengths,
    const int* __restrict__ target_lengths,
    float*     __restrict__ out)
{
    const unsigned FULL = 0xffffffffu;
    const int tid  = threadIdx.x;
    const int warp = tid >> 5;
    const int lane = tid & 31;
    const int n    = blockIdx.x * 4 + warp;

    const int tl = target_lengths[n];
    const int pl = pred_lengths[n];
    const int Sv = 2 * tl + 1;
    const int s0 = 3 * lane;

    bool valid[3], skip[3];
    #pragma unroll
    for (int j = 0; j < 3; j++) {
        int s = s0 + j;
        valid[j] = (s < S_) && (s < Sv);
        bool sk = false;
        if (s < S_ && (s & 1) && s >= 2) {
            int lab  = targets[n * L_ + (s >> 1)];
            int lab2 = targets[n * L_ + (s >> 1) - 1];
            sk = (lab != BLANK_) && (lab != lab2);
        }
        skip[j] = sk;
    }

    const float* __restrict__ pn = g_p_ext + n * (TP_ * S_);

    // alpha0 (linear domain); invalid/unreached states = 0
    float alpha[3];
    {
        float p0 = pn[0];
        float p1 = pn[1];
        #pragma unroll
        for (int j = 0; j < 3; j++) {
            int s = s0 + j;
            float a0 = 0.0f;
            if (s == 0) a0 = p0;
            if (s == 1 && tl > 0) a0 = p1;
            alpha[j] = valid[j] ? a0 : 0.0f;
        }
    }
    int E = 0;   // alpha_true = alpha * 2^E  (uniform across warp)

    // preload pipeline: rows t = 1..8
    float lp[8][3];
    #pragma unroll
    for (int j = 0; j < 8; j++) {
        const float* r = pn + (1 + j) * S_ + s0;
        lp[j][0] = r[0]; lp[j][1] = r[1]; lp[j][2] = r[2];
    }

    #pragma unroll 8
    for (int t = 1; t <= 256; t++) {
        const int u = (t - 1) & 7;
        float l0 = lp[u][0], l1 = lp[u][1], l2 = lp[u][2];

        // refill slot with row t+8 (padded scratch keeps addresses in bounds)
        {
            const float* r = pn + (t + 8) * S_ + s0;
            lp[u][0] = r[0]; lp[u][1] = r[1]; lp[u][2] = r[2];
        }

        float nb1 = __shfl_up_sync(FULL, alpha[1], 1);  // state s0-2
        float nb2 = __shfl_up_sync(FULL, alpha[2], 1);  // state s0-1
        if (lane == 0) { nb1 = 0.0f; nb2 = 0.0f; }

        float c0 = alpha[0] + nb2      + (skip[0] ? nb1      : 0.0f);
        float c1 = alpha[1] + alpha[0] + (skip[1] ? nb2      : 0.0f);
        float c2 = alpha[2] + alpha[1] + (skip[2] ? alpha[0] : 0.0f);

        if (t < pl && t < T_) {
            alpha[0] = valid[0] ? (c0 * l0) : 0.0f;
            alpha[1] = valid[1] ? (c1 * l1) : 0.0f;
            alpha[2] = valid[2] ? (c2 * l2) : 0.0f;
        }

        // periodic renormalization: keep warp-max exponent near 0
        if ((t & 3) == 0) {
            float mx = fmaxf(fmaxf(alpha[0], alpha[1]), alpha[2]);
            unsigned mb = redux_max_u32(__float_as_uint(mx));
            if (mb >= 0x00800000u) {     // max is a normal float
                int e = (int)(mb >> 23) - 127;
                float scale = __uint_as_float((unsigned)(127 - e) << 23); // 2^-e
                alpha[0] *= scale; alpha[1] *= scale; alpha[2] *= scale;
                E += e;
            }
        }
    }

    // extract alpha[end], alpha[end-1] (end = 2*tl, uniform within warp)
    const int end = 2 * tl;
    const int le = end / 3, je = end % 3;
    float v0 = __shfl_sync(FULL, alpha[0], le);
    float v1 = __shfl_sync(FULL, alpha[1], le);
    float v2 = __shfl_sync(FULL, alpha[2], le);
    float a_last = (je == 0) ? v0 : (je == 1) ? v1 : v2;

    const int ep = (end > 0) ? end - 1 : 0;
    const int lpl = ep / 3, jp = ep % 3;
    float w0 = __shfl_sync(FULL, alpha[0], lpl);
    float w1 = __shfl_sync(FULL, alpha[1], lpl);
    float w2 = __shfl_sync(FULL, alpha[2], lpl);
    float a_prev = (jp == 0) ? w0 : (jp == 1) ? w1 : w2;
    if (tl <= 0) a_prev = 0.0f;

    if (lane == 0) {
        float sum = a_last + a_prev;
        float nll = -(logf(sum) + (float)E * LN2);   // logf(0) -> -inf -> guarded
        if (!isfinite(nll) || nll >= 1e29f) nll = 0.0f;
        int denom = tl > 0 ? tl : 1;
        g_per_n[n] = nll / (float)denom;
    }

    // last-block-done finalize: no waiting, no deadlock possible
    __syncthreads();
    if (tid == 0) {
        __threadfence();                               // publish this block's g_per_n
        unsigned old = atomicAdd(&g_blkdone, 1u);
        if (old == (unsigned)(gridDim.x - 1)) {
            __threadfence();                           // order reads after observation
            float acc = 0.0f;
            #pragma unroll
            for (int i = 0; i < N_; i++) acc += ldcg_f(g_per_n + i);
            out[0] = acc / (float)N_;
            g_blkdone = 0u;                            // reset for next replay
        }
    }
}

extern "C" void kernel_launch(void* const* d_in, const int* in_sizes, int n_in,
                              void* d_out, int out_size)
{
    const float* preds          = (const float*)d_in[0];
    const int*   targets        = (const int*)d_in[1];
    const int*   pred_lengths   = (const int*)d_in[2];
    const int*   target_lengths = (const int*)d_in[3];
    float* out = (float*)d_out;

    lse_gather_kernel<<<T_ * N_, 256>>>(preds, targets);
    ctc_forward_kernel<<<N_ / 4, 128>>>(targets, pred_lengths, target_lengths, out);
}

// round 7
// speedup vs baseline: 1.7002x; 1.1411x over previous
#include <cuda_runtime.h>
#include <math.h>

#define T_ 256
#define N_ 64
#define C_ 4096
#define L_ 32
#define S_ 65           // 2*L+1
#define BLANK_ 0
#define LOG2E 1.4426950408889634f
#define LN2   0.6931471805599453f

#define TP_ (T_ + 16)   // padded T so the depth-8 forward pipeline never loads OOB

// Scratch, layout [n][t][s]: LINEAR probabilities of the 65 extended labels.
__device__ float g_p_ext[N_ * TP_ * S_ + 128];
__device__ float g_per_n[N_];
__device__ unsigned g_blkdone;   // zero-init; reset by last block each run

__device__ __forceinline__ float ex2(float x) {
    float y; asm("ex2.approx.ftz.f32 %0, %1;" : "=f"(y) : "f"(x)); return y;
}
__device__ __forceinline__ float lg2(float x) {
    float y; asm("lg2.approx.ftz.f32 %0, %1;" : "=f"(y) : "f"(x)); return y;
}
__device__ __forceinline__ float ldcg_f(const float* p) {
    float v; asm volatile("ld.global.cg.f32 %0, [%1];" : "=f"(v) : "l"(p)); return v;
}
__device__ __forceinline__ unsigned redux_max_u32(unsigned v) {
    unsigned r;
    asm volatile("redux.sync.max.u32 %0, %1, 0xffffffff;" : "=r"(r) : "r"(v));
    return r;
}

// skip flag for extended state s of batch n: odd s >= 3 with label != prev label
__device__ __forceinline__ bool skip_at(const int* __restrict__ targets, int n, int s) {
    if (s < S_ && (s & 1) && s >= 2) {
        int lab  = targets[n * L_ + (s >> 1)];
        int lab2 = targets[n * L_ + (s >> 1) - 1];
        return (lab != BLANK_) && (lab != lab2);
    }
    return false;
}

// Kernel 1: per (t,n) row of 4096 -> logsumexp -> gather 65 extended-label
// LINEAR probabilities into g_p_ext[n][t][s]. Proven at HBM roofline.
__global__ void __launch_bounds__(256) lse_gather_kernel(
    const float* __restrict__ preds, const int* __restrict__ targets)
{
    const unsigned FULL = 0xffffffffu;
    const int row = blockIdx.x;        // row = t*N + n  (preds is (T,N,C))
    const int t   = row / N_;
    const int n   = row % N_;
    const float* __restrict__ p = preds + (size_t)row * C_;
    const int tid = threadIdx.x;

    float v[16];
    const float4* __restrict__ p4 = (const float4*)p;
    #pragma unroll
    for (int k = 0; k < 4; k++) {
        float4 f = p4[tid + k * 256];
        v[k*4+0] = f.x; v[k*4+1] = f.y; v[k*4+2] = f.z; v[k*4+3] = f.w;
    }

    float m = v[0];
    #pragma unroll
    for (int i = 1; i < 16; i++) m = fmaxf(m, v[i]);
    #pragma unroll
    for (int o = 16; o > 0; o >>= 1) m = fmaxf(m, __shfl_xor_sync(FULL, m, o));
    __shared__ float sm[8];
    if ((tid & 31) == 0) sm[tid >> 5] = m;
    __syncthreads();
    float bm = sm[0];
    #pragma unroll
    for (int i = 1; i < 8; i++) bm = fmaxf(bm, sm[i]);
    __syncthreads();

    const float bmL = bm * LOG2E;
    float s = 0.0f;
    #pragma unroll
    for (int i = 0; i < 16; i++) s += ex2(fmaf(v[i], LOG2E, -bmL));
    #pragma unroll
    for (int o = 16; o > 0; o >>= 1) s += __shfl_xor_sync(FULL, s, o);
    if ((tid & 31) == 0) sm[tid >> 5] = s;
    __syncthreads();
    float bs = sm[0];
    #pragma unroll
    for (int i = 1; i < 8; i++) bs += sm[i];

    const float lse = bm + lg2(bs) * LN2;

    if (tid < S_) {
        int label = (tid & 1) ? targets[n * L_ + (tid >> 1)] : BLANK_;
        g_p_ext[(n * TP_ + t) * S_ + tid] = ex2((p[label] - lse) * LOG2E);
    }
}

// Kernel 2: fwd/bwd split CTC recursion (linear domain, exponent-tracked).
// Block = 8 warps; warps 0-3 run FORWARD (t=1..127) for n = blk*4+w,
// warps 4-7 run BACKWARD (t=255..128) for the same n. Combine: P = <g, alpha>.
__global__ void __launch_bounds__(256) ctc_forward_kernel(
    const int* __restrict__ targets,
    const int* __restrict__ pred_lengths,
    const int* __restrict__ target_lengths,
    float*     __restrict__ out)
{
    const unsigned FULL = 0xffffffffu;
    const int tid  = threadIdx.x;
    const int warp = tid >> 5;
    const int lane = tid & 31;
    const int w    = warp & 3;          // pair index
    const bool fwd = (warp < 4);
    const int n    = blockIdx.x * 4 + w;

    const int tl = target_lengths[n];
    const int pl = pred_lengths[n];
    const int Sv = 2 * tl + 1;
    const int s0 = 3 * lane;

    __shared__ float sA[4][96];
    __shared__ float sG[4][96];
    __shared__ int   sE[4][2];          // [w][0]=E_fwd, [w][1]=E_bwd

    bool valid[3];
    #pragma unroll
    for (int j = 0; j < 3; j++) valid[j] = ((s0 + j) < S_) && ((s0 + j) < Sv);

    const float* __restrict__ pn = g_p_ext + n * (TP_ * S_);
    float a[3];
    int E = 0;
    float lp[8][3];

    if (fwd) {
        // skip flags for own states (gates the s-2 jump INTO state s)
        bool skip[3];
        #pragma unroll
        for (int j = 0; j < 3; j++) skip[j] = skip_at(targets, n, s0 + j);

        // alpha0
        {
            float p0 = pn[0], p1 = pn[1];
            #pragma unroll
            for (int j = 0; j < 3; j++) {
                int s = s0 + j;
                float a0 = 0.0f;
                if (s == 0) a0 = p0;
                if (s == 1 && tl > 0) a0 = p1;
                a[j] = valid[j] ? a0 : 0.0f;
            }
        }

        // preload rows t = 1..8
        #pragma unroll
        for (int j = 0; j < 8; j++) {
            const float* r = pn + (1 + j) * S_ + s0;
            lp[j][0] = r[0]; lp[j][1] = r[1]; lp[j][2] = r[2];
        }

        #pragma unroll 8
        for (int t = 1; t <= 128; t++) {
            const int u = (t - 1) & 7;
            float l0 = lp[u][0], l1 = lp[u][1], l2 = lp[u][2];
            {
                const float* r = pn + (t + 8) * S_ + s0;   // padded, in-bounds
                lp[u][0] = r[0]; lp[u][1] = r[1]; lp[u][2] = r[2];
            }

            float nb1 = __shfl_up_sync(FULL, a[1], 1);   // state s0-2
            float nb2 = __shfl_up_sync(FULL, a[2], 1);   // state s0-1
            if (lane == 0) { nb1 = 0.0f; nb2 = 0.0f; }

            float c0 = a[0] + nb2  + (skip[0] ? nb1  : 0.0f);
            float c1 = a[1] + a[0] + (skip[1] ? nb2  : 0.0f);
            float c2 = a[2] + a[1] + (skip[2] ? a[0] : 0.0f);

            if (t < 128 && t < pl) {      // apply steps 1..127 only
                a[0] = valid[0] ? (c0 * l0) : 0.0f;
                a[1] = valid[1] ? (c1 * l1) : 0.0f;
                a[2] = valid[2] ? (c2 * l2) : 0.0f;
            }

            if ((t & 3) == 0) {
                float mx = fmaxf(fmaxf(a[0], a[1]), a[2]);
                unsigned mb = redux_max_u32(__float_as_uint(mx));
                if (mb >= 0x00800000u) {
                    int e = (int)(mb >> 23) - 127;
                    float sc = __uint_as_float((unsigned)(127 - e) << 23);
                    a[0] *= sc; a[1] *= sc; a[2] *= sc;
                    E += e;
                }
            }
        }
        sA[w][s0] = a[0]; sA[w][s0 + 1] = a[1]; sA[w][s0 + 2] = a[2];
        if (lane == 0) sE[w][0] = E;
    } else {
        // skip flags for states s0+2..s0+4 (gates the s->s+2 jump OUT of s)
        bool sk2 = skip_at(targets, n, s0 + 2);
        bool sk3 = skip_at(targets, n, s0 + 3);
        bool sk4 = skip_at(targets, n, s0 + 4);

        // g init = endpoint indicator f (no p multiply; loop applies D_255 first)
        const int end = 2 * tl;
        #pragma unroll
        for (int j = 0; j < 3; j++) {
            int s = s0 + j;
            float g0 = 0.0f;
            if (s == end) g0 = 1.0f;
            if (tl > 0 && s == end - 1) g0 = 1.0f;
            a[j] = valid[j] ? g0 : 0.0f;
        }

        // preload rows t = 255..248
        #pragma unroll
        for (int j = 0; j < 8; j++) {
            const float* r = pn + (255 - j) * S_ + s0;
            lp[j][0] = r[0]; lp[j][1] = r[1]; lp[j][2] = r[2];
        }

        #pragma unroll 8
        for (int td = 0; td < 128; td++) {
            const int u = td & 7;
            const int t = 255 - td;
            float l0 = lp[u][0], l1 = lp[u][1], l2 = lp[u][2];
            {
                const float* r = pn + (t - 8) * S_ + s0;   // t-8 >= 120, in-bounds
                lp[u][0] = r[0]; lp[u][1] = r[1]; lp[u][2] = r[2];
            }

            float h0 = a[0] * l0;
            float h1 = a[1] * l1;
            float h2 = a[2] * l2;
            float hd0 = __shfl_down_sync(FULL, h0, 1);   // state s0+3
            float hd1 = __shfl_down_sync(FULL, h1, 1);   // state s0+4
            if (lane == 31) { hd0 = 0.0f; hd1 = 0.0f; }

            if (t < pl) {
                a[0] = valid[0] ? (h0 + h1  + (sk2 ? h2  : 0.0f)) : 0.0f;
                a[1] = valid[1] ? (h1 + h2  + (sk3 ? hd0 : 0.0f)) : 0.0f;
                a[2] = valid[2] ? (h2 + hd0 + (sk4 ? hd1 : 0.0f)) : 0.0f;
            }

            if ((td & 3) == 3) {
                float mx = fmaxf(fmaxf(a[0], a[1]), a[2]);
                unsigned mb = redux_max_u32(__float_as_uint(mx));
                if (mb >= 0x00800000u) {
                    int e = (int)(mb >> 23) - 127;
                    float sc = __uint_as_float((unsigned)(127 - e) << 23);
                    a[0] *= sc; a[1] *= sc; a[2] *= sc;
                    E += e;
                }
            }
        }
        sG[w][s0] = a[0]; sG[w][s0 + 1] = a[1]; sG[w][s0 + 2] = a[2];
        if (lane == 0) sE[w][1] = E;
    }

    __syncthreads();

    // combine (forward warps): P = <g_128, alpha_127> * 2^(Ef+Eb)
    if (fwd) {
        float dot = sA[w][s0]     * sG[w][s0]
                  + sA[w][s0 + 1] * sG[w][s0 + 1]
                  + sA[w][s0 + 2] * sG[w][s0 + 2];
        #pragma unroll
        for (int o = 16; o > 0; o >>= 1) dot += __shfl_xor_sync(FULL, dot, o);

        if (lane == 0) {
            float nll = -(logf(dot) + (float)(sE[w][0] + sE[w][1]) * LN2);
            if (!isfinite(nll) || nll >= 1e29f) nll = 0.0f;
            int denom = tl > 0 ? tl : 1;
            g_per_n[n] = nll / (float)denom;
        }
    }

    // last-block-done finalize (non-blocking)
    __syncthreads();
    if (tid == 0) {
        __threadfence();
        unsigned old = atomicAdd(&g_blkdone, 1u);
        if (old == (unsigned)(gridDim.x - 1)) {
            __threadfence();
            float acc = 0.0f;
            #pragma unroll
            for (int i = 0; i < N_; i++) acc += ldcg_f(g_per_n + i);
            out[0] = acc / (float)N_;
            g_blkdone = 0u;
        }
    }
}

extern "C" void kernel_launch(void* const* d_in, const int* in_sizes, int n_in,
                              void* d_out, int out_size)
{
    const float* preds          = (const float*)d_in[0];
    const int*   targets        = (const int*)d_in[1];
    const int*   pred_lengths   = (const int*)d_in[2];
    const int*   target_lengths = (const int*)d_in[3];
    float* out = (float*)d_out;

    lse_gather_kernel<<<T_ * N_, 256>>>(preds, targets);
    ctc_forward_kernel<<<N_ / 4, 256>>>(targets, pred_lengths, target_lengths, out);
}

// round 12
// speedup vs baseline: 2.0123x; 1.1836x over previous
#include <cuda_runtime.h>
#include <math.h>

#define T_ 256
#define N_ 64
#define C_ 4096
#define L_ 32
#define S_ 65           // 2*L+1
#define BLANK_ 0
#define LOG2E 1.4426950408889634f
#define LN2   0.6931471805599453f

#define TP_ (T_ + 16)   // padded T so the depth-8 forward pipeline never loads OOB

// Scratch, layout [n][t][s]: LINEAR probabilities of the 65 extended labels.
__device__ __align__(16) float g_p_ext[N_ * TP_ * S_ + 128];
__device__ float g_per_n[N_];
__device__ unsigned g_blkdone;   // zero-init; reset by last block each run

__device__ __forceinline__ float ex2(float x) {
    float y; asm("ex2.approx.ftz.f32 %0, %1;" : "=f"(y) : "f"(x)); return y;
}
__device__ __forceinline__ float lg2(float x) {
    float y; asm("lg2.approx.ftz.f32 %0, %1;" : "=f"(y) : "f"(x)); return y;
}
__device__ __forceinline__ float ldcg_f(const float* p) {
    float v; asm volatile("ld.global.cg.f32 %0, [%1];" : "=f"(v) : "l"(p)); return v;
}
__device__ __forceinline__ unsigned redux_max_u32(unsigned v) {
    unsigned r;
    asm volatile("redux.sync.max.u32 %0, %1, 0xffffffff;" : "=r"(r) : "r"(v));
    return r;
}

// skip flag for extended state s of batch n: odd s >= 3 with label != prev label
__device__ __forceinline__ bool skip_at(const int* __restrict__ targets, int n, int s) {
    if (s < S_ && (s & 1) && s >= 2) {
        int lab  = targets[n * L_ + (s >> 1)];
        int lab2 = targets[n * L_ + (s >> 1) - 1];
        return (lab != BLANK_) && (lab != lab2);
    }
    return false;
}

// Kernel 1: per (t,n) row of 4096 -> logsumexp -> gather 65 extended-label
// LINEAR probabilities into g_p_ext[n][t][s]. At HBM roofline. preds is read
// with .cs (streaming, evict-first) so the scratch stays L2-resident.
__global__ void __launch_bounds__(256) lse_gather_kernel(
    const float* __restrict__ preds, const int* __restrict__ targets)
{
    const unsigned FULL = 0xffffffffu;
    const int row = blockIdx.x;        // row = t*N + n  (preds is (T,N,C))
    const int t   = row / N_;
    const int n   = row % N_;
    const float* __restrict__ p = preds + (size_t)row * C_;
    const int tid = threadIdx.x;

    float v[16];
    const float4* __restrict__ p4 = (const float4*)p;
    #pragma unroll
    for (int k = 0; k < 4; k++) {
        float4 f = __ldcs(p4 + tid + k * 256);     // ld.global.cs.v4.f32
        v[k*4+0] = f.x; v[k*4+1] = f.y; v[k*4+2] = f.z; v[k*4+3] = f.w;
    }

    float m = v[0];
    #pragma unroll
    for (int i = 1; i < 16; i++) m = fmaxf(m, v[i]);
    #pragma unroll
    for (int o = 16; o > 0; o >>= 1) m = fmaxf(m, __shfl_xor_sync(FULL, m, o));
    __shared__ float sm[8];
    if ((tid & 31) == 0) sm[tid >> 5] = m;
    __syncthreads();
    float bm = sm[0];
    #pragma unroll
    for (int i = 1; i < 8; i++) bm = fmaxf(bm, sm[i]);
    __syncthreads();

    const float bmL = bm * LOG2E;
    float s = 0.0f;
    #pragma unroll
    for (int i = 0; i < 16; i++) s += ex2(fmaf(v[i], LOG2E, -bmL));
    #pragma unroll
    for (int o = 16; o > 0; o >>= 1) s += __shfl_xor_sync(FULL, s, o);
    if ((tid & 31) == 0) sm[tid >> 5] = s;
    __syncthreads();
    float bs = sm[0];
    #pragma unroll
    for (int i = 1; i < 8; i++) bs += sm[i];

    const float lse = bm + lg2(bs) * LN2;

    if (tid < S_) {
        int label = (tid & 1) ? targets[n * L_ + (tid >> 1)] : BLANK_;
        g_p_ext[(n * TP_ + t) * S_ + tid] = ex2((p[label] - lse) * LOG2E);
    }
}

// Kernel 2: fwd/bwd split CTC recursion (linear domain, exponent-tracked).
// Block = 8 warps; warps 0-3 run FORWARD (t=1..127) for n = blk*4+w,
// warps 4-7 run BACKWARD (t=255..128) for the same n. Combine: P = <g, alpha>.
// (Byte-identical to the round-7 kernel that passed at rel_err 1.4e-6.)
__global__ void __launch_bounds__(256) ctc_forward_kernel(
    const int* __restrict__ targets,
    const int* __restrict__ pred_lengths,
    const int* __restrict__ target_lengths,
    float*     __restrict__ out)
{
    const unsigned FULL = 0xffffffffu;
    const int tid  = threadIdx.x;
    const int warp = tid >> 5;
    const int lane = tid & 31;
    const int w    = warp & 3;          // pair index
    const bool fwd = (warp < 4);
    const int n    = blockIdx.x * 4 + w;

    const int tl = target_lengths[n];
    const int pl = pred_lengths[n];
    const int Sv = 2 * tl + 1;
    const int s0 = 3 * lane;

    __shared__ float sA[4][96];
    __shared__ float sG[4][96];
    __shared__ int   sE[4][2];          // [w][0]=E_fwd, [w][1]=E_bwd

    bool valid[3];
    #pragma unroll
    for (int j = 0; j < 3; j++) valid[j] = ((s0 + j) < S_) && ((s0 + j) < Sv);

    const float* __restrict__ pn = g_p_ext + n * (TP_ * S_);
    float a[3];
    int E = 0;
    float lp[8][3];

    if (fwd) {
        bool skip[3];
        #pragma unroll
        for (int j = 0; j < 3; j++) skip[j] = skip_at(targets, n, s0 + j);

        // alpha0
        {
            float p0 = pn[0], p1 = pn[1];
            #pragma unroll
            for (int j = 0; j < 3; j++) {
                int s = s0 + j;
                float a0 = 0.0f;
                if (s == 0) a0 = p0;
                if (s == 1 && tl > 0) a0 = p1;
                a[j] = valid[j] ? a0 : 0.0f;
            }
        }

        // preload rows t = 1..8
        #pragma unroll
        for (int j = 0; j < 8; j++) {
            const float* r = pn + (1 + j) * S_ + s0;
            lp[j][0] = r[0]; lp[j][1] = r[1]; lp[j][2] = r[2];
        }

        #pragma unroll 8
        for (int t = 1; t <= 128; t++) {
            const int u = (t - 1) & 7;
            float l0 = lp[u][0], l1 = lp[u][1], l2 = lp[u][2];
            {
                const float* r = pn + (t + 8) * S_ + s0;   // padded, in-bounds
                lp[u][0] = r[0]; lp[u][1] = r[1]; lp[u][2] = r[2];
            }

            float nb1 = __shfl_up_sync(FULL, a[1], 1);   // state s0-2
            float nb2 = __shfl_up_sync(FULL, a[2], 1);   // state s0-1
            if (lane == 0) { nb1 = 0.0f; nb2 = 0.0f; }

            float c0 = a[0] + nb2  + (skip[0] ? nb1  : 0.0f);
            float c1 = a[1] + a[0] + (skip[1] ? nb2  : 0.0f);
            float c2 = a[2] + a[1] + (skip[2] ? a[0] : 0.0f);

            if (t < 128 && t < pl) {      // apply steps 1..127 only
                a[0] = valid[0] ? (c0 * l0) : 0.0f;
                a[1] = valid[1] ? (c1 * l1) : 0.0f;
                a[2] = valid[2] ? (c2 * l2) : 0.0f;
            }

            if ((t & 3) == 0) {
                float mx = fmaxf(fmaxf(a[0], a[1]), a[2]);
                unsigned mb = redux_max_u32(__float_as_uint(mx));
                if (mb >= 0x00800000u) {
                    int e = (int)(mb >> 23) - 127;
                    float sc = __uint_as_float((unsigned)(127 - e) << 23);
                    a[0] *= sc; a[1] *= sc; a[2] *= sc;
                    E += e;
                }
            }
        }
        sA[w][s0] = a[0]; sA[w][s0 + 1] = a[1]; sA[w][s0 + 2] = a[2];
        if (lane == 0) sE[w][0] = E;
    } else {
        bool sk2 = skip_at(targets, n, s0 + 2);
        bool sk3 = skip_at(targets, n, s0 + 3);
        bool sk4 = skip_at(targets, n, s0 + 4);

        // g init = endpoint indicator
        const int end = 2 * tl;
        #pragma unroll
        for (int j = 0; j < 3; j++) {
            int s = s0 + j;
            float g0 = 0.0f;
            if (s == end) g0 = 1.0f;
            if (tl > 0 && s == end - 1) g0 = 1.0f;
            a[j] = valid[j] ? g0 : 0.0f;
        }

        // preload rows t = 255..248
        #pragma unroll
        for (int j = 0; j < 8; j++) {
            const float* r = pn + (255 - j) * S_ + s0;
            lp[j][0] = r[0]; lp[j][1] = r[1]; lp[j][2] = r[2];
        }

        #pragma unroll 8
        for (int td = 0; td < 128; td++) {
            const int u = td & 7;
            const int t = 255 - td;
            float l0 = lp[u][0], l1 = lp[u][1], l2 = lp[u][2];
            {
                const float* r = pn + (t - 8) * S_ + s0;   // t-8 >= 120, in-bounds
                lp[u][0] = r[0]; lp[u][1] = r[1]; lp[u][2] = r[2];
            }

            float h0 = a[0] * l0;
            float h1 = a[1] * l1;
            float h2 = a[2] * l2;
            float hd0 = __shfl_down_sync(FULL, h0, 1);   // state s0+3
            float hd1 = __shfl_down_sync(FULL, h1, 1);   // state s0+4
            if (lane == 31) { hd0 = 0.0f; hd1 = 0.0f; }

            if (t < pl) {
                a[0] = valid[0] ? (h0 + h1  + (sk2 ? h2  : 0.0f)) : 0.0f;
                a[1] = valid[1] ? (h1 + h2  + (sk3 ? hd0 : 0.0f)) : 0.0f;
                a[2] = valid[2] ? (h2 + hd0 + (sk4 ? hd1 : 0.0f)) : 0.0f;
            }

            if ((td & 3) == 3) {
                float mx = fmaxf(fmaxf(a[0], a[1]), a[2]);
                unsigned mb = redux_max_u32(__float_as_uint(mx));
                if (mb >= 0x00800000u) {
                    int e = (int)(mb >> 23) - 127;
                    float sc = __uint_as_float((unsigned)(127 - e) << 23);
                    a[0] *= sc; a[1] *= sc; a[2] *= sc;
                    E += e;
                }
            }
        }
        sG[w][s0] = a[0]; sG[w][s0 + 1] = a[1]; sG[w][s0 + 2] = a[2];
        if (lane == 0) sE[w][1] = E;
    }

    __syncthreads();

    // combine (forward warps): P = <g_128, alpha_127> * 2^(Ef+Eb)
    if (fwd) {
        float dot = sA[w][s0]     * sG[w][s0]
                  + sA[w][s0 + 1] * sG[w][s0 + 1]
                  + sA[w][s0 + 2] * sG[w][s0 + 2];
        #pragma unroll
        for (int o = 16; o > 0; o >>= 1) dot += __shfl_xor_sync(FULL, dot, o);

        if (lane == 0) {
            float nll = -(logf(dot) + (float)(sE[w][0] + sE[w][1]) * LN2);
            if (!isfinite(nll) || nll >= 1e29f) nll = 0.0f;
            int denom = tl > 0 ? tl : 1;
            g_per_n[n] = nll / (float)denom;
        }
    }

    // last-block-done finalize (non-blocking)
    __syncthreads();
    if (tid == 0) {
        __threadfence();
        unsigned old = atomicAdd(&g_blkdone, 1u);
        if (old == (unsigned)(gridDim.x - 1)) {
            __threadfence();
            float acc = 0.0f;
            #pragma unroll
            for (int i = 0; i < N_; i++) acc += ldcg_f(g_per_n + i);
            out[0] = acc / (float)N_;
            g_blkdone = 0u;
        }
    }
}

extern "C" void kernel_launch(void* const* d_in, const int* in_sizes, int n_in,
                              void* d_out, int out_size)
{
    const float* preds          = (const float*)d_in[0];
    const int*   targets        = (const int*)d_in[1];
    const int*   pred_lengths   = (const int*)d_in[2];
    const int*   target_lengths = (const int*)d_in[3];
    float* out = (float*)d_out;

    lse_gather_kernel<<<T_ * N_, 256>>>(preds, targets);
    ctc_forward_kernel<<<N_ / 4, 256>>>(targets, pred_lengths, target_lengths, out);
}

// round 13
// speedup vs baseline: 2.0949x; 1.0411x over previous
#include <cuda_runtime.h>
#include <math.h>

#define T_ 256
#define N_ 64
#define C_ 4096
#define L_ 32
#define S_ 65           // 2*L+1
#define BLANK_ 0
#define LOG2E 1.4426950408889634f
#define LN2   0.6931471805599453f

#define TP_ (T_ + 16)   // padded T (fwd prefetch reaches row 144 max; in-bounds)
#define DEPTH 16        // load-pipeline depth: 16 * ~55cyc > 577cyc DRAM latency

// Scratch, layout [n][t][s]: LINEAR probabilities of the 65 extended labels.
__device__ __align__(16) float g_p_ext[N_ * TP_ * S_ + 128];
__device__ float g_per_n[N_];
__device__ unsigned g_blkdone;   // zero-init; reset by last block each run

__device__ __forceinline__ float ex2(float x) {
    float y; asm("ex2.approx.ftz.f32 %0, %1;" : "=f"(y) : "f"(x)); return y;
}
__device__ __forceinline__ float lg2(float x) {
    float y; asm("lg2.approx.ftz.f32 %0, %1;" : "=f"(y) : "f"(x)); return y;
}
__device__ __forceinline__ float ldcg_f(const float* p) {
    float v; asm volatile("ld.global.cg.f32 %0, [%1];" : "=f"(v) : "l"(p)); return v;
}
__device__ __forceinline__ unsigned redux_max_u32(unsigned v) {
    unsigned r;
    asm volatile("redux.sync.max.u32 %0, %1, 0xffffffff;" : "=r"(r) : "r"(v));
    return r;
}

// skip flag for extended state s of batch n: odd s >= 3 with label != prev label
__device__ __forceinline__ bool skip_at(const int* __restrict__ targets, int n, int s) {
    if (s < S_ && (s & 1) && s >= 2) {
        int lab  = targets[n * L_ + (s >> 1)];
        int lab2 = targets[n * L_ + (s >> 1) - 1];
        return (lab != BLANK_) && (lab != lab2);
    }
    return false;
}

// Kernel 1: per (t,n) row of 4096 -> logsumexp -> gather 65 extended-label
// LINEAR probabilities into g_p_ext[n][t][s]. preds read with .cs (streaming).
// Proven at/near HBM roofline (~32us in round 12).
__global__ void __launch_bounds__(256) lse_gather_kernel(
    const float* __restrict__ preds, const int* __restrict__ targets)
{
    const unsigned FULL = 0xffffffffu;
    const int row = blockIdx.x;        // row = t*N + n  (preds is (T,N,C))
    const int t   = row / N_;
    const int n   = row % N_;
    const float* __restrict__ p = preds + (size_t)row * C_;
    const int tid = threadIdx.x;

    float v[16];
    const float4* __restrict__ p4 = (const float4*)p;
    #pragma unroll
    for (int k = 0; k < 4; k++) {
        float4 f = __ldcs(p4 + tid + k * 256);     // ld.global.cs.v4.f32
        v[k*4+0] = f.x; v[k*4+1] = f.y; v[k*4+2] = f.z; v[k*4+3] = f.w;
    }

    float m = v[0];
    #pragma unroll
    for (int i = 1; i < 16; i++) m = fmaxf(m, v[i]);
    #pragma unroll
    for (int o = 16; o > 0; o >>= 1) m = fmaxf(m, __shfl_xor_sync(FULL, m, o));
    __shared__ float sm[8];
    if ((tid & 31) == 0) sm[tid >> 5] = m;
    __syncthreads();
    float bm = sm[0];
    #pragma unroll
    for (int i = 1; i < 8; i++) bm = fmaxf(bm, sm[i]);
    __syncthreads();

    const float bmL = bm * LOG2E;
    float s = 0.0f;
    #pragma unroll
    for (int i = 0; i < 16; i++) s += ex2(fmaf(v[i], LOG2E, -bmL));
    #pragma unroll
    for (int o = 16; o > 0; o >>= 1) s += __shfl_xor_sync(FULL, s, o);
    if ((tid & 31) == 0) sm[tid >> 5] = s;
    __syncthreads();
    float bs = sm[0];
    #pragma unroll
    for (int i = 1; i < 8; i++) bs += sm[i];

    const float lse = bm + lg2(bs) * LN2;

    if (tid < S_) {
        int label = (tid & 1) ? targets[n * L_ + (tid >> 1)] : BLANK_;
        g_p_ext[(n * TP_ + t) * S_ + tid] = ex2((p[label] - lse) * LOG2E);
    }
}

// Kernel 2: fwd/bwd split CTC recursion (linear domain, exponent-tracked).
// One block per batch n, 64 threads: warp 0 FORWARD (t=1..127), warp 1
// BACKWARD (t=255..128). Depth-16 register pipeline hides DRAM latency.
// Recursion arithmetic identical to the round-7/12 kernels (rel 1.4e-6).
__global__ void __launch_bounds__(64) ctc_forward_kernel(
    const int* __restrict__ targets,
    const int* __restrict__ pred_lengths,
    const int* __restrict__ target_lengths,
    float*     __restrict__ out)
{
    const unsigned FULL = 0xffffffffu;
    const int tid  = threadIdx.x;
    const int warp = tid >> 5;
    const int lane = tid & 31;
    const bool fwd = (warp == 0);
    const int n    = blockIdx.x;

    const int tl = target_lengths[n];
    const int pl = pred_lengths[n];
    const int Sv = 2 * tl + 1;
    const int s0 = 3 * lane;

    __shared__ float sA[96];
    __shared__ float sG[96];
    __shared__ int   sE[2];             // [0]=E_fwd, [1]=E_bwd

    bool valid[3];
    #pragma unroll
    for (int j = 0; j < 3; j++) valid[j] = ((s0 + j) < S_) && ((s0 + j) < Sv);

    const float* __restrict__ pn = g_p_ext + n * (TP_ * S_);
    float a[3];
    int E = 0;
    float lp[DEPTH][3];

    if (fwd) {
        bool skip[3];
        #pragma unroll
        for (int j = 0; j < 3; j++) skip[j] = skip_at(targets, n, s0 + j);

        // alpha0
        {
            float p0 = pn[0], p1 = pn[1];
            #pragma unroll
            for (int j = 0; j < 3; j++) {
                int s = s0 + j;
                float a0 = 0.0f;
                if (s == 0) a0 = p0;
                if (s == 1 && tl > 0) a0 = p1;
                a[j] = valid[j] ? a0 : 0.0f;
            }
        }

        // preload rows t = 1..DEPTH
        #pragma unroll
        for (int j = 0; j < DEPTH; j++) {
            const float* r = pn + (1 + j) * S_ + s0;
            lp[j][0] = r[0]; lp[j][1] = r[1]; lp[j][2] = r[2];
        }

        #pragma unroll 16
        for (int t = 1; t <= 128; t++) {
            const int u = (t - 1) & (DEPTH - 1);
            float l0 = lp[u][0], l1 = lp[u][1], l2 = lp[u][2];
            {
                const float* r = pn + (t + DEPTH) * S_ + s0;  // max row 144 < TP_
                lp[u][0] = r[0]; lp[u][1] = r[1]; lp[u][2] = r[2];
            }

            float nb1 = __shfl_up_sync(FULL, a[1], 1);   // state s0-2
            float nb2 = __shfl_up_sync(FULL, a[2], 1);   // state s0-1
            if (lane == 0) { nb1 = 0.0f; nb2 = 0.0f; }

            float c0 = a[0] + nb2  + (skip[0] ? nb1  : 0.0f);
            float c1 = a[1] + a[0] + (skip[1] ? nb2  : 0.0f);
            float c2 = a[2] + a[1] + (skip[2] ? a[0] : 0.0f);

            if (t < 128 && t < pl) {      // apply steps 1..127 only
                a[0] = valid[0] ? (c0 * l0) : 0.0f;
                a[1] = valid[1] ? (c1 * l1) : 0.0f;
                a[2] = valid[2] ? (c2 * l2) : 0.0f;
            }

            if ((t & 3) == 0) {
                float mx = fmaxf(fmaxf(a[0], a[1]), a[2]);
                unsigned mb = redux_max_u32(__float_as_uint(mx));
                if (mb >= 0x00800000u) {
                    int e = (int)(mb >> 23) - 127;
                    float sc = __uint_as_float((unsigned)(127 - e) << 23);
                    a[0] *= sc; a[1] *= sc; a[2] *= sc;
                    E += e;
                }
            }
        }
        sA[s0] = a[0]; sA[s0 + 1] = a[1]; sA[s0 + 2] = a[2];
        if (lane == 0) sE[0] = E;
    } else {
        bool sk2 = skip_at(targets, n, s0 + 2);
        bool sk3 = skip_at(targets, n, s0 + 3);
        bool sk4 = skip_at(targets, n, s0 + 4);

        // g init = endpoint indicator
        const int end = 2 * tl;
        #pragma unroll
        for (int j = 0; j < 3; j++) {
            int s = s0 + j;
            float g0 = 0.0f;
            if (s == end) g0 = 1.0f;
            if (tl > 0 && s == end - 1) g0 = 1.0f;
            a[j] = valid[j] ? g0 : 0.0f;
        }

        // preload rows t = 255..240
        #pragma unroll
        for (int j = 0; j < DEPTH; j++) {
            const float* r = pn + (255 - j) * S_ + s0;
            lp[j][0] = r[0]; lp[j][1] = r[1]; lp[j][2] = r[2];
        }

        #pragma unroll 16
        for (int td = 0; td < 128; td++) {
            const int u = td & (DEPTH - 1);
            const int t = 255 - td;
            float l0 = lp[u][0], l1 = lp[u][1], l2 = lp[u][2];
            {
                const float* r = pn + (t - DEPTH) * S_ + s0;  // min row 112 >= 0
                lp[u][0] = r[0]; lp[u][1] = r[1]; lp[u][2] = r[2];
            }

            float h0 = a[0] * l0;
            float h1 = a[1] * l1;
            float h2 = a[2] * l2;
            float hd0 = __shfl_down_sync(FULL, h0, 1);   // state s0+3
            float hd1 = __shfl_down_sync(FULL, h1, 1);   // state s0+4
            if (lane == 31) { hd0 = 0.0f; hd1 = 0.0f; }

            if (t < pl) {
                a[0] = valid[0] ? (h0 + h1  + (sk2 ? h2  : 0.0f)) : 0.0f;
                a[1] = valid[1] ? (h1 + h2  + (sk3 ? hd0 : 0.0f)) : 0.0f;
                a[2] = valid[2] ? (h2 + hd0 + (sk4 ? hd1 : 0.0f)) : 0.0f;
            }

            if ((td & 3) == 3) {
                float mx = fmaxf(fmaxf(a[0], a[1]), a[2]);
                unsigned mb = redux_max_u32(__float_as_uint(mx));
                if (mb >= 0x00800000u) {
                    int e = (int)(mb >> 23) - 127;
                    float sc = __uint_as_float((unsigned)(127 - e) << 23);
                    a[0] *= sc; a[1] *= sc; a[2] *= sc;
                    E += e;
                }
            }
        }
        sG[s0] = a[0]; sG[s0 + 1] = a[1]; sG[s0 + 2] = a[2];
        if (lane == 0) sE[1] = E;
    }

    __syncthreads();

    // combine (warp 0): P = <alpha_127, g_128> * 2^(Ef+Eb)
    if (fwd) {
        float dot = sA[s0]     * sG[s0]
                  + sA[s0 + 1] * sG[s0 + 1]
                  + sA[s0 + 2] * sG[s0 + 2];
        #pragma unroll
        for (int o = 16; o > 0; o >>= 1) dot += __shfl_xor_sync(FULL, dot, o);

        if (lane == 0) {
            float nll = -(logf(dot) + (float)(sE[0] + sE[1]) * LN2);
            if (!isfinite(nll) || nll >= 1e29f) nll = 0.0f;
            int denom = tl > 0 ? tl : 1;
            g_per_n[n] = nll / (float)denom;
        }
    }

    // last-block-done finalize (non-blocking, single-writer fence pattern)
    __syncthreads();
    if (tid == 0) {
        __threadfence();
        unsigned old = atomicAdd(&g_blkdone, 1u);
        if (old == (unsigned)(gridDim.x - 1)) {
            __threadfence();
            float acc = 0.0f;
            #pragma unroll
            for (int i = 0; i < N_; i++) acc += ldcg_f(g_per_n + i);
            out[0] = acc / (float)N_;
            g_blkdone = 0u;
        }
    }
}

extern "C" void kernel_launch(void* const* d_in, const int* in_sizes, int n_in,
                              void* d_out, int out_size)
{
    const float* preds          = (const float*)d_in[0];
    const int*   targets        = (const int*)d_in[1];
    const int*   pred_lengths   = (const int*)d_in[2];
    const int*   target_lengths = (const int*)d_in[3];
    float* out = (float*)d_out;

    lse_gather_kernel<<<T_ * N_, 256>>>(preds, targets);
    ctc_forward_kernel<<<N_, 64>>>(targets, pred_lengths, target_lengths, out);
}